// round 10
// baseline (speedup 1.0000x reference)
#include <cuda_runtime.h>

// ---------------- problem constants ----------------
#define NN     12288
#define INFEAT 128
#define OF     64
#define AL     0.2f

// ---------------- main-kernel tiling ----------------
#define JSPLIT 3
#define JSL    (NN / JSPLIT)     /* 4096 columns per block */
#define TJ     32                /* j-tile */
#define NTILE  (JSL / TJ)        /* 128 tiles */
#define RB     128               /* rows per block */
#define NRB    (NN / RB)         /* 96 row-blocks */
#define RP     138               /* Psm row pad: 8B-align planes, 2-phase STS */
#define PSTR   68                /* partial stride: 64 feats + den + pad */

// ---------------- device scratch (static globals: allowed) ----------------
__device__ __align__(16) float  g_h[NN * OF];                        // 3 MB
__device__ float  g_c[NN];
__device__ float  g_d[NN];
__device__ __align__(16) float4 g_rowc[NN];    // (-c_i, A_i, A'_i, 0)
__device__ __align__(16) float4 g_scalJ[NN];   // (d_j, B_j, B'_j, 0)
__device__ __align__(16) float  g_part[(size_t)JSPLIT * NN * PSTR];  // 10 MB
__device__ unsigned g_dmax_enc;

// monotone float<->unsigned encode for atomicMax over signed floats
__device__ __forceinline__ unsigned fenc(float f) {
    unsigned b = __float_as_uint(f);
    return (b & 0x80000000u) ? ~b : (b | 0x80000000u);
}
__device__ __forceinline__ float fdec(unsigned u) {
    return (u & 0x80000000u) ? __uint_as_float(u & 0x7fffffffu)
                             : __uint_as_float(~u);
}

__device__ __forceinline__ unsigned su(const void* p) {
    unsigned r;
    asm("{ .reg .u64 t; cvta.to.shared.u64 t, %1; cvt.u32.u64 %0, t; }"
        : "=r"(r) : "l"(p));
    return r;
}

#define FMA2(acc_, a_, b_) \
    asm("fma.rn.f32x2 %0, %1, %2, %0;" : "+l"(acc_) : "l"(a_), "l"(b_))

// ---------------- K0: reset dmax atomic (replay-safe) ----------------
__global__ void k_reset() { g_dmax_enc = 0u; }

// ---------------- K1: h = input @ W  (16 rows/block, 256 thr) --------
__global__ void __launch_bounds__(256) k_linear(const float* __restrict__ x,
                                                const float* __restrict__ W) {
    __shared__ __align__(16) float Wsm[INFEAT * OF];  // 32 KB
    __shared__ __align__(16) float Xsm[16 * INFEAT];  // 8 KB
    int tid = threadIdx.x;
    int i0  = blockIdx.x * 16;

    const float4* Wg  = (const float4*)W;
    float4*       Ws4 = (float4*)Wsm;
    #pragma unroll
    for (int e = tid; e < INFEAT * OF / 4; e += 256) Ws4[e] = Wg[e];

    const float4* Xg  = (const float4*)(x + (size_t)i0 * INFEAT);
    float4*       Xs4 = (float4*)Xsm;
    #pragma unroll
    for (int e = tid; e < 16 * INFEAT / 4; e += 256) Xs4[e] = Xg[e];
    __syncthreads();

    int f  = tid & 63;
    int rt = tid >> 6;  // 0..3 -> 4 rows each
    float acc[4] = {0.f, 0.f, 0.f, 0.f};
    #pragma unroll 4
    for (int k = 0; k < INFEAT; k++) {
        float w = Wsm[k * OF + f];
        #pragma unroll
        for (int j = 0; j < 4; j++)
            acc[j] += Xsm[(rt * 4 + j) * INFEAT + k] * w;
    }
    #pragma unroll
    for (int j = 0; j < 4; j++)
        g_h[(size_t)(i0 + rt * 4 + j) * OF + f] = acc[j];
}

// ---------------- K2: c_i = h_i.a1, d_i = h_i.a2, global dmax --------
__global__ void __launch_bounds__(256) k_attvec(const float* __restrict__ a) {
    __shared__ float sred[8];
    int tid  = threadIdx.x;
    int lane = tid & 31, wid = tid >> 5;
    int i = blockIdx.x * 8 + wid;
    float h0 = g_h[(size_t)i * OF + lane];
    float h1 = g_h[(size_t)i * OF + 32 + lane];
    float c = h0 * __ldg(a + lane)      + h1 * __ldg(a + 32 + lane);
    float d = h0 * __ldg(a + 64 + lane) + h1 * __ldg(a + 96 + lane);
    #pragma unroll
    for (int s = 16; s; s >>= 1) {
        c += __shfl_xor_sync(0xffffffffu, c, s);
        d += __shfl_xor_sync(0xffffffffu, d, s);
    }
    if (lane == 0) { g_c[i] = c; g_d[i] = d; sred[wid] = d; }
    __syncthreads();
    if (tid == 0) {
        float m = sred[0];
        #pragma unroll
        for (int w = 1; w < 8; w++) m = fmaxf(m, sred[w]);
        atomicMax(&g_dmax_enc, fenc(m));
    }
}

// ---------------- K3: per-row / per-col softmax factors --------------
__global__ void __launch_bounds__(256) k_factors() {
    int i = blockIdx.x * 256 + threadIdx.x;
    float dmax = fdec(g_dmax_enc);
    float c = g_c[i], d = g_d[i];
    float cm = c + dmax;
    float s = cm > 0.f ? cm : AL * cm;          // s_i = lrelu(c_i + dmax)
    g_rowc[i]  = make_float4(-c, expf(cm - s), expf(AL * cm - s), 0.f);
    float dm = d - dmax;
    g_scalJ[i] = make_float4(d, expf(dm), expf(AL * dm), 0.f);
}

// ---------------- K4: main fused masked-softmax-weighted aggregation --
// block (rb, js): rows rb*128..+127, cols js*4096..+4095
// phase1: adj -> p -> Psm[j][row] (transposed) + den
// phase2: acc[rowpair][feat] += {p_r,p_r+1} * {h_f,h_f}  via fma.rn.f32x2
__global__ void __launch_bounds__(128) k_main(const int* __restrict__ adj) {
    __shared__ __align__(16) float Psm[TJ * RP];      // 17664 B
    __shared__ __align__(16) float Hd[TJ * OF * 2];   // duplicated h: 16 KB
    __shared__ float Den[RB];

    int tid = threadIdx.x;
    int rowbase = blockIdx.x * RB;
    int js = blockIdx.y;
    int jbase = js * JSL;

    // phase-1 ids
    int s  = tid & 7;        // 8 j-segments of 4 (one int4)
    int rr = tid >> 3;       // 0..15 -> row within pass
    // phase-2 ids
    int fg = tid & 7;        // feat group (8 feats)
    int rg = tid >> 3;       // row group (8 rows), 0..15

    unsigned psmU = su(Psm), hdU = su(Hd);
    unsigned pBase0 = psmU + (unsigned)(rg * 8 * 4);  // + jl*RP*4
    unsigned hBase0 = hdU + (unsigned)(fg * 64);      // + jl*512

    unsigned long long acc[32];
    #pragma unroll
    for (int i = 0; i < 32; i++) acc[i] = 0ull;
    if (tid < RB) Den[tid] = 0.f;

    for (int T = 0; T < NTILE; T++) {
        int j0 = jbase + T * TJ;
        __syncthreads();  // previous tile's phase-2 done with smem

        // ---- fill Hd (dup): thread: jl = tid>>2, q = tid&3 (16 feats)
        {
            int jl = tid >> 2, q = tid & 3;
            const float4* hp = (const float4*)(g_h + (size_t)(j0 + jl) * OF) + q * 4;
            float4* dp = ((float4*)Hd) + jl * (OF / 2) + q * 8;
            #pragma unroll
            for (int u = 0; u < 4; u++) {
                float4 v = hp[u];
                dp[2 * u]     = make_float4(v.x, v.x, v.y, v.y);
                dp[2 * u + 1] = make_float4(v.z, v.z, v.w, v.w);
            }
        }

        // ---- per-thread column factors (global, L1/L2 hot)
        float4 sc[4];
        #pragma unroll
        for (int e = 0; e < 4; e++) sc[e] = __ldg(g_scalJ + j0 + s * 4 + e);

        // ---- adj prefetch (8 int4 = 32 cols x 8 passes of 16 rows)
        const int4* ap = (const int4*)(adj + (size_t)rowbase * NN + j0) + s;
        int4 av[8];
        #pragma unroll
        for (int p = 0; p < 8; p++)
            av[p] = ap[(size_t)(p * 16 + rr) * (NN / 4)];

        // ---- compute P tile + den
        #pragma unroll
        for (int p = 0; p < 8; p++) {
            int row = p * 16 + rr;
            float4 rc = __ldg(g_rowc + rowbase + row);
            int a4[4] = {av[p].x, av[p].y, av[p].z, av[p].w};
            float psum = 0.f;
            float pv[4];
            #pragma unroll
            for (int e = 0; e < 4; e++) {
                float4 s4 = sc[e];
                bool  pos = s4.x > rc.x;                  // d_j > -c_i
                float fa  = pos ? rc.y : rc.z;
                float fb  = pos ? s4.y : s4.z;
                float pp  = (a4[e] != 0) ? fa * fb : 0.f;
                pv[e] = pp;
                psum += pp;
            }
            #pragma unroll
            for (int e = 0; e < 4; e++)
                Psm[(s * 4 + e) * RP + row] = pv[e];
            psum += __shfl_down_sync(0xffffffffu, psum, 4, 8);
            psum += __shfl_down_sync(0xffffffffu, psum, 2, 8);
            psum += __shfl_down_sync(0xffffffffu, psum, 1, 8);
            if (s == 0) Den[row] += psum;   // unique owner per row, no race
        }
        __syncthreads();

        // ---- phase 2: register GEMM over 32 j's
        unsigned pA = pBase0, hA = hBase0;
        #pragma unroll 2
        for (int jl = 0; jl < TJ; jl++) {
            unsigned long long p0, p1, p2, p3, hh[8];
            asm volatile("ld.shared.b64 %0,[%1];" : "=l"(p0) : "r"(pA));
            asm volatile("ld.shared.b64 %0,[%1];" : "=l"(p1) : "r"(pA + 8));
            asm volatile("ld.shared.b64 %0,[%1];" : "=l"(p2) : "r"(pA + 16));
            asm volatile("ld.shared.b64 %0,[%1];" : "=l"(p3) : "r"(pA + 24));
            asm volatile("ld.shared.v2.b64 {%0,%1},[%2];" : "=l"(hh[0]), "=l"(hh[1]) : "r"(hA));
            asm volatile("ld.shared.v2.b64 {%0,%1},[%2];" : "=l"(hh[2]), "=l"(hh[3]) : "r"(hA + 16));
            asm volatile("ld.shared.v2.b64 {%0,%1},[%2];" : "=l"(hh[4]), "=l"(hh[5]) : "r"(hA + 32));
            asm volatile("ld.shared.v2.b64 {%0,%1},[%2];" : "=l"(hh[6]), "=l"(hh[7]) : "r"(hA + 48));
            #pragma unroll
            for (int t = 0; t < 8; t++) {
                FMA2(acc[t],      p0, hh[t]);
                FMA2(acc[8 + t],  p1, hh[t]);
                FMA2(acc[16 + t], p2, hh[t]);
                FMA2(acc[24 + t], p3, hh[t]);
            }
            pA += RP * 4;
            hA += 512;
        }
    }

    // ---- write partials (no atomics, unique writer per element)
    float* part = g_part + (size_t)js * NN * PSTR;
    #pragma unroll
    for (int k = 0; k < 4; k++) {
        int r0 = rowbase + rg * 8 + 2 * k;
        #pragma unroll
        for (int t = 0; t < 8; t++) {
            float lo, hi;
            asm("mov.b64 {%0,%1}, %2;" : "=f"(lo), "=f"(hi) : "l"(acc[k * 8 + t]));
            part[(size_t)r0 * PSTR + fg * 8 + t]       = lo;
            part[(size_t)(r0 + 1) * PSTR + fg * 8 + t] = hi;
        }
    }
    if (tid < RB)
        part[(size_t)(rowbase + tid) * PSTR + OF] = Den[tid];
}

// ---------------- K5: reduce partials, divide, elu -------------------
__global__ void __launch_bounds__(256) k_out(float* __restrict__ out) {
    int idx = blockIdx.x * 256 + threadIdx.x;   // < NN*OF
    int row = idx >> 6, f = idx & 63;
    size_t base = (size_t)row * PSTR;
    float num = 0.f, den = 0.f;
    #pragma unroll
    for (int js = 0; js < JSPLIT; js++) {
        const float* p = g_part + (size_t)js * NN * PSTR + base;
        num += p[f];
        den += p[OF];
    }
    float v = num / den;
    out[idx] = v > 0.f ? v : expm1f(v);
}

// ---------------- launch ----------------
extern "C" void kernel_launch(void* const* d_in, const int* in_sizes, int n_in,
                              void* d_out, int out_size) {
    (void)out_size;
    const float* input = nullptr;
    const int*   adj   = nullptr;
    const float* W     = nullptr;
    const float* a     = nullptr;
    for (int i = 0; i < n_in; i++) {
        switch (in_sizes[i]) {
            case NN * INFEAT:        input = (const float*)d_in[i]; break;
            case INFEAT * OF:        W     = (const float*)d_in[i]; break;
            case 2 * OF:             a     = (const float*)d_in[i]; break;
            default:
                if ((long long)in_sizes[i] == (long long)NN * NN)
                    adj = (const int*)d_in[i];
                break;
        }
    }
    if (!input) input = (const float*)d_in[0];
    if (!adj)   adj   = (const int*)d_in[1];
    if (!W)     W     = (const float*)d_in[2];
    if (!a)     a     = (const float*)d_in[3];

    k_reset<<<1, 1>>>();
    k_linear<<<NN / 16, 256>>>(input, W);
    k_attvec<<<NN / 8, 256>>>(a);
    k_factors<<<NN / 256, 256>>>();
    k_main<<<dim3(NRB, JSPLIT), 128>>>(adj);
    k_out<<<NN * OF / 256, 256>>>((float*)d_out);
}

// round 16
// speedup vs baseline: 4.2313x; 4.2313x over previous
#include <cuda_runtime.h>
#include <cuda_fp16.h>
#include <cstdint>

#define NN 12288
#define INFEAT 128
#define OF 64
#define AL 0.2f

#define JSPLIT 3
#define KSL (NN/JSPLIT)   /* 4096 */
#define KT 64
#define NT (KSL/KT)       /* 64 */
#define RB 128
#define NRB (NN/RB)       /* 96 */
#define NGT (NN/KT)       /* 192 */
#define PSTR 68
#define HTB 9216          /* one H variant tile: 72 rows x 128B */
#define HTILE (2*HTB)

/* smem layout (relative to 1024-aligned base) */
#define SP_PHI 0
#define SP_PLO 16384
#define SP_H   32768
#define SP_RC  51200
#define SMEM_DYN (51200 + 2048 + 1024)

// ---------------- device scratch ----------------
__device__ __align__(16) float  g_h[NN * OF];
__device__ float  g_c[NN];
__device__ float  g_d[NN];
__device__ __align__(16) float4 g_rowc[NN];   // (-c, A, A', 0)
__device__ __align__(16) float4 g_scalJ[NN];  // (d, B, B', 0)
__device__ __align__(16) float  g_part[(size_t)JSPLIT * NN * PSTR];
__device__ __align__(16) unsigned char g_Ht[(size_t)NGT * HTILE];  // 3.5 MB
__device__ unsigned g_dmax_enc;

// ---------------- helpers ----------------
__device__ __forceinline__ unsigned fenc(float f) {
    unsigned b = __float_as_uint(f);
    return (b & 0x80000000u) ? ~b : (b | 0x80000000u);
}
__device__ __forceinline__ float fdec(unsigned u) {
    return (u & 0x80000000u) ? __uint_as_float(u & 0x7fffffffu)
                             : __uint_as_float(~u);
}
__device__ __forceinline__ unsigned su(const void* p) {
    unsigned r;
    asm("{ .reg .u64 t; cvta.to.shared.u64 t, %1; cvt.u32.u64 %0, t; }"
        : "=r"(r) : "l"(p));
    return r;
}
__device__ __forceinline__ void ldsm4(unsigned* r, unsigned a) {
    asm volatile("ldmatrix.sync.aligned.m8n8.x4.shared.b16 {%0,%1,%2,%3}, [%4];"
                 : "=r"(r[0]), "=r"(r[1]), "=r"(r[2]), "=r"(r[3]) : "r"(a));
}
__device__ __forceinline__ void ldsm2(unsigned* r, unsigned a) {
    asm volatile("ldmatrix.sync.aligned.m8n8.x2.shared.b16 {%0,%1}, [%2];"
                 : "=r"(r[0]), "=r"(r[1]) : "r"(a));
}
__device__ __forceinline__ void mma16816(float* c, const unsigned* a,
                                         unsigned b0, unsigned b1) {
    asm volatile("mma.sync.aligned.m16n8k16.row.col.f32.f16.f16.f32 "
                 "{%0,%1,%2,%3}, {%4,%5,%6,%7}, {%8,%9}, {%0,%1,%2,%3};"
                 : "+f"(c[0]), "+f"(c[1]), "+f"(c[2]), "+f"(c[3])
                 : "r"(a[0]), "r"(a[1]), "r"(a[2]), "r"(a[3]),
                   "r"(b0), "r"(b1));
}

// ---------------- K0 ----------------
__global__ void k_reset() { g_dmax_enc = 0u; }

// ---------------- K1: h = input @ W ----------------
__global__ void __launch_bounds__(256) k_linear(const float* __restrict__ x,
                                                const float* __restrict__ W) {
    __shared__ __align__(16) float Wsm[INFEAT * OF];
    __shared__ __align__(16) float Xsm[16 * INFEAT];
    int tid = threadIdx.x, i0 = blockIdx.x * 16;
    const float4* Wg = (const float4*)W;
    float4* Ws4 = (float4*)Wsm;
    #pragma unroll
    for (int e = tid; e < INFEAT * OF / 4; e += 256) Ws4[e] = Wg[e];
    const float4* Xg = (const float4*)(x + (size_t)i0 * INFEAT);
    float4* Xs4 = (float4*)Xsm;
    #pragma unroll
    for (int e = tid; e < 16 * INFEAT / 4; e += 256) Xs4[e] = Xg[e];
    __syncthreads();
    int f = tid & 63, rt = tid >> 6;
    float acc[4] = {0.f, 0.f, 0.f, 0.f};
    #pragma unroll 4
    for (int k = 0; k < INFEAT; k++) {
        float w = Wsm[k * OF + f];
        #pragma unroll
        for (int j = 0; j < 4; j++) acc[j] += Xsm[(rt * 4 + j) * INFEAT + k] * w;
    }
    #pragma unroll
    for (int j = 0; j < 4; j++) g_h[(size_t)(i0 + rt * 4 + j) * OF + f] = acc[j];
}

// ---------------- K2: c, d, dmax ----------------
__global__ void __launch_bounds__(256) k_attvec(const float* __restrict__ a) {
    __shared__ float sred[8];
    int tid = threadIdx.x, lane = tid & 31, wid = tid >> 5;
    int i = blockIdx.x * 8 + wid;
    float h0 = g_h[(size_t)i * OF + lane];
    float h1 = g_h[(size_t)i * OF + 32 + lane];
    float c = h0 * __ldg(a + lane) + h1 * __ldg(a + 32 + lane);
    float d = h0 * __ldg(a + 64 + lane) + h1 * __ldg(a + 96 + lane);
    #pragma unroll
    for (int s = 16; s; s >>= 1) {
        c += __shfl_xor_sync(0xffffffffu, c, s);
        d += __shfl_xor_sync(0xffffffffu, d, s);
    }
    if (lane == 0) { g_c[i] = c; g_d[i] = d; sred[wid] = d; }
    __syncthreads();
    if (tid == 0) {
        float m = sred[0];
        #pragma unroll
        for (int w = 1; w < 8; w++) m = fmaxf(m, sred[w]);
        atomicMax(&g_dmax_enc, fenc(m));
    }
}

// ---------------- K3: softmax factors ----------------
__global__ void __launch_bounds__(256) k_factors() {
    int i = blockIdx.x * 256 + threadIdx.x;
    float dmax = fdec(g_dmax_enc);
    float c = g_c[i], d = g_d[i];
    float cm = c + dmax;
    float s = cm > 0.f ? cm : AL * cm;
    g_rowc[i]  = make_float4(-c, expf(cm - s), expf(AL * cm - s), 0.f);
    float dm = d - dmax;
    g_scalJ[i] = make_float4(d, expf(dm), expf(AL * dm), 0.f);
}

// ---------------- K3b: H tiles [n72][k64] fp16 hi/lo, pre-swizzled ----
__global__ void __launch_bounds__(128) k_hprep() {
    int gt = blockIdx.x;
    size_t tb = (size_t)gt * HTILE;
    for (int e = threadIdx.x; e < 72 * 64; e += 128) {
        int n = e >> 6, k = e & 63;
        float hv;
        if (n < OF) hv = g_h[(size_t)(gt * KT + k) * OF + n];
        else hv = (n == OF) ? 1.f : 0.f;
        __half hh = __float2half_rn(hv);
        __half hl = __float2half_rn(hv - __half2float(hh));
        unsigned off = (unsigned)(n * 128 + k * 2);
        unsigned sw = off ^ ((off >> 3) & 0x70);
        *(__half*)(g_Ht + tb + sw) = hh;
        *(__half*)(g_Ht + tb + HTB + sw) = hl;
    }
}

// ---------------- K4: main — P build + mma.sync HMMA GEMM ----------------
__global__ void __launch_bounds__(256, 2) k_main(const int* __restrict__ adj) {
    extern __shared__ char dynsm[];
    char* sb = (char*)((((uintptr_t)dynsm) + 1023u) & ~(uintptr_t)1023u);
    unsigned base = su(sb);
    int tid = threadIdx.x, lane = tid & 31, w = tid >> 5;
    int rowbase = blockIdx.x * RB, js = blockIdx.y;

    // stage row factors once
    if (tid < RB) ((float4*)(sb + SP_RC))[tid] = __ldg(&g_rowc[rowbase + tid]);

    // phase-1 ids: 16 threads cover one row's 64-col chunk (4 int4 each)
    int c16 = tid & 15;      // int4 chunk within row (4 j's)
    int rsub = tid >> 4;     // 0..15

    // A-frag address constants (m16k16 ldmatrix.x4)
    int mA = w * 16 + ((lane >> 3) & 1) * 8 + (lane & 7);
    unsigned offA0 = (unsigned)(mA * 128 + (lane >> 4) * 16);
    unsigned xA = (unsigned)((mA & 7) << 4);
    // B-frag lane decomposition
    int nrow_in = lane & 7;
    int half_n = (lane >> 4) & 1;
    int kcB = (lane >> 3) & 1;
    // den (n-tile 8) x2
    int nD = 64 + (lane & 7);
    unsigned offD0 = (unsigned)(nD * 128 + ((lane >> 3) & 1) * 16);
    unsigned xD = (unsigned)((nD & 7) << 4);

    float acc[9][4];
    #pragma unroll
    for (int i = 0; i < 9; i++)
        #pragma unroll
        for (int q = 0; q < 4; q++) acc[i][q] = 0.f;

    const int4* adj4 = (const int4*)adj;
    const size_t rowstr = NN / 4;
    const size_t abase0 = (size_t)(rowbase + rsub) * rowstr + (size_t)c16;

    for (int T = 0; T < NT; T++) {
        int gt = js * NT + T;
        int j0 = gt * KT;
        __syncthreads();

        // adj prefetch: 8 coalesced int4 (MLP=8)
        int4 av[8];
        {
            size_t ab = abase0 + (size_t)(j0 >> 2);
            #pragma unroll
            for (int p = 0; p < 8; p++)
                av[p] = __ldg(adj4 + ab + (size_t)(p * 16) * rowstr);
        }

        // copy pre-swizzled H tile (hi+lo, 18 KB, L2-hot)
        {
            const float4* src = (const float4*)(g_Ht + (size_t)gt * HTILE);
            float4* dst = (float4*)(sb + SP_H);
            for (int e = tid; e < HTILE / 16; e += 256) dst[e] = __ldg(src + e);
        }

        // column factors for this thread's 4 j's
        float4 sc[4];
        #pragma unroll
        for (int e = 0; e < 4; e++) sc[e] = __ldg(&g_scalJ[j0 + c16 * 4 + e]);

        // build P tile (hi/lo fp16) in smem
        #pragma unroll
        for (int p = 0; p < 8; p++) {
            int m = p * 16 + rsub;
            float4 rc = ((const float4*)(sb + SP_RC))[m];
            int ai[4] = {av[p].x, av[p].y, av[p].z, av[p].w};
            float pv[4];
            #pragma unroll
            for (int e = 0; e < 4; e++) {
                bool pos = sc[e].x > rc.x;            // d_j > -c_i
                float fa = pos ? rc.y : rc.z;
                float fb = pos ? sc[e].y : sc[e].z;
                pv[e] = (ai[e] != 0) ? fa * fb : 0.f;
            }
            __half h0 = __float2half_rn(pv[0]), h1 = __float2half_rn(pv[1]);
            __half h2 = __float2half_rn(pv[2]), h3 = __float2half_rn(pv[3]);
            unsigned hi01 = (unsigned)__half_as_ushort(h0) |
                            ((unsigned)__half_as_ushort(h1) << 16);
            unsigned hi23 = (unsigned)__half_as_ushort(h2) |
                            ((unsigned)__half_as_ushort(h3) << 16);
            __half l0 = __float2half_rn(pv[0] - __half2float(h0));
            __half l1 = __float2half_rn(pv[1] - __half2float(h1));
            __half l2 = __float2half_rn(pv[2] - __half2float(h2));
            __half l3 = __float2half_rn(pv[3] - __half2float(h3));
            unsigned lo01 = (unsigned)__half_as_ushort(l0) |
                            ((unsigned)__half_as_ushort(l1) << 16);
            unsigned lo23 = (unsigned)__half_as_ushort(l2) |
                            ((unsigned)__half_as_ushort(l3) << 16);
            unsigned off = (unsigned)(m * 128 + c16 * 8);
            unsigned sw = off ^ ((off >> 3) & 0x70);
            asm volatile("st.shared.v2.b32 [%0], {%1,%2};"
                         :: "r"(base + SP_PHI + sw), "r"(hi01), "r"(hi23) : "memory");
            asm volatile("st.shared.v2.b32 [%0], {%1,%2};"
                         :: "r"(base + SP_PLO + sw), "r"(lo01), "r"(lo23) : "memory");
        }
        __syncthreads();

        // MMA phase: 4 k-steps x (8 feat n-tiles + den), 3 products (drop lo*lo)
        #pragma unroll
        for (int s = 0; s < 4; s++) {
            unsigned aoff = (offA0 + (unsigned)(s * 32)) ^ xA;
            unsigned ahi[4], alo[4];
            ldsm4(ahi, base + SP_PHI + aoff);
            ldsm4(alo, base + SP_PLO + aoff);
            #pragma unroll
            for (int pi = 0; pi < 4; pi++) {
                int nB = pi * 16 + half_n * 8 + nrow_in;
                unsigned offB = (unsigned)(nB * 128 + kcB * 16 + s * 32);
                unsigned aB = offB ^ (unsigned)((nB & 7) << 4);
                unsigned bhi[4], blo[4];
                ldsm4(bhi, base + SP_H + aB);
                ldsm4(blo, base + SP_H + HTB + aB);
                mma16816(acc[2 * pi],     ahi, bhi[0], bhi[1]);
                mma16816(acc[2 * pi],     ahi, blo[0], blo[1]);
                mma16816(acc[2 * pi],     alo, bhi[0], bhi[1]);
                mma16816(acc[2 * pi + 1], ahi, bhi[2], bhi[3]);
                mma16816(acc[2 * pi + 1], ahi, blo[2], blo[3]);
                mma16816(acc[2 * pi + 1], alo, bhi[2], bhi[3]);
            }
            {
                unsigned aD = (offD0 + (unsigned)(s * 32)) ^ xD;
                unsigned bh[2], bl[2];
                ldsm2(bh, base + SP_H + aD);
                ldsm2(bl, base + SP_H + HTB + aD);
                mma16816(acc[8], ahi, bh[0], bh[1]);
                mma16816(acc[8], ahi, bl[0], bl[1]);
                mma16816(acc[8], alo, bh[0], bh[1]);
            }
        }
    }

    // ---- epilogue: write partials (unique writer per element) ----
    {
        int r0 = rowbase + w * 16 + (lane >> 2);
        int r1 = r0 + 8;
        int cb = (lane & 3) * 2;
        float* pt = g_part + (size_t)js * NN * PSTR;
        #pragma unroll
        for (int nn = 0; nn < 8; nn++) {
            *(float2*)(pt + (size_t)r0 * PSTR + nn * 8 + cb) =
                make_float2(acc[nn][0], acc[nn][1]);
            *(float2*)(pt + (size_t)r1 * PSTR + nn * 8 + cb) =
                make_float2(acc[nn][2], acc[nn][3]);
        }
        if ((lane & 3) == 0) {
            pt[(size_t)r0 * PSTR + OF] = acc[8][0];
            pt[(size_t)r1 * PSTR + OF] = acc[8][2];
        }
    }
}

// ---------------- K5: reduce partials, divide, elu ----------------
__global__ void __launch_bounds__(256) k_out(float* __restrict__ out) {
    int idx = blockIdx.x * 256 + threadIdx.x;
    int row = idx >> 6, f = idx & 63;
    size_t bpos = (size_t)row * PSTR;
    float num = 0.f, den = 0.f;
    #pragma unroll
    for (int js = 0; js < JSPLIT; js++) {
        const float* p = g_part + (size_t)js * NN * PSTR + bpos;
        num += p[f];
        den += p[OF];
    }
    float v = num / den;
    out[idx] = v > 0.f ? v : expm1f(v);
}

// ---------------- launch ----------------
extern "C" void kernel_launch(void* const* d_in, const int* in_sizes, int n_in,
                              void* d_out, int out_size) {
    (void)out_size;
    const float* input = nullptr;
    const int*   adj   = nullptr;
    const float* W     = nullptr;
    const float* a     = nullptr;
    for (int i = 0; i < n_in; i++) {
        switch (in_sizes[i]) {
            case NN * INFEAT: input = (const float*)d_in[i]; break;
            case INFEAT * OF: W     = (const float*)d_in[i]; break;
            case 2 * OF:      a     = (const float*)d_in[i]; break;
            default:
                if ((long long)in_sizes[i] == (long long)NN * NN)
                    adj = (const int*)d_in[i];
                break;
        }
    }
    if (!input) input = (const float*)d_in[0];
    if (!adj)   adj   = (const int*)d_in[1];
    if (!W)     W     = (const float*)d_in[2];
    if (!a)     a     = (const float*)d_in[3];

    // Unconditional (idempotent, deterministic; stream-independent so
    // graph-capture-safe).
    cudaFuncSetAttribute(k_main, cudaFuncAttributeMaxDynamicSharedMemorySize,
                         SMEM_DYN);

    k_reset<<<1, 1>>>();
    k_linear<<<NN / 16, 256>>>(input, W);
    k_attvec<<<NN / 8, 256>>>(a);
    k_factors<<<NN / 256, 256>>>();
    k_hprep<<<NGT, 128>>>();
    k_main<<<dim3(NRB, JSPLIT), 256, SMEM_DYN>>>(adj);
    k_out<<<NN * OF / 256, 256>>>((float*)d_out);
}